// round 11
// baseline (speedup 1.0000x reference)
#include <cuda_runtime.h>
#include <cuda_fp16.h>
#include <math.h>

#define NLV 16
#define NDENSE 8
#define NHASH 8
#define TSZ (1u << 19)
#define TMASK (TSZ - 1u)
#define P1 2654435761u
#define P2 805459861u
#define P3 3674653429u
#define FSCALE 256.0f
#define INV_FSCALE (1.0f / 256.0f)

// Dense yz-quad grids, x-fastest, fp16x4 per 16B cell. Levels 0..7: ~5.85M cells.
#define DENSE_CAP 6000000
#define POS_CAP   2100000
__device__ uint4  g_dense[DENSE_CAP];          // 96 MB
__device__ unsigned g_htab[NHASH << 19];       // fp16x2 copies of tables 8..15 (16 MB)
__device__ float4 g_pos4[POS_CAP];             // packed positions (32 MB)

struct LvlParams {
    int res[NLV];
    int dofs[NDENSE];    // cell offset per dense level
    int soff[NDENSE];    // staging thread offset per dense level (4x4 blocks)
};

__device__ __forceinline__ unsigned h2u(half2 h) { return *reinterpret_cast<unsigned*>(&h); }
__device__ __forceinline__ float2 u2f(unsigned u) {
    half2 h = *reinterpret_cast<half2*>(&u);
    return __half22float2(h);
}

// ---------------------------------------------------------------------------
// Fused staging kernel. Blocks are striped proportionally between two
// independent segments so the DRAM-bound copy overlaps the l1tex-bound
// dense build:
//   dense blocks : build dense grids, thread = (level, x, 4x4 yz cell block),
//                  rows streamed (25 gathers -> up to 16 cells)
//   copy blocks  : htab fp16 conversion (4 entries/thread) + pos packing
// ---------------------------------------------------------------------------
__global__ void __launch_bounds__(256) stage_fused_kernel(
    const float2* __restrict__ tables,
    const float*  __restrict__ pos,
    LvlParams lp, int htot, int npts, int stot, unsigned db, unsigned T)
{
    unsigned b = blockIdx.x;
    unsigned d_here = (unsigned)(((unsigned long long)b * db) / T);
    unsigned d_next = (unsigned)(((unsigned long long)(b + 1) * db) / T);

    if (d_next == d_here) {
        // ---- copy segment ----
        int i = (int)(b - d_here) * 256 + threadIdx.x;
        if (i < htot) {
            const float4* src = reinterpret_cast<const float4*>(tables + ((size_t)8 << 19));
            float4 v01 = __ldg(src + (size_t)i * 2);
            float4 v23 = __ldg(src + (size_t)i * 2 + 1);
            uint4 q;
            q.x = h2u(__floats2half2_rn(v01.x * FSCALE, v01.y * FSCALE));
            q.y = h2u(__floats2half2_rn(v01.z * FSCALE, v01.w * FSCALE));
            q.z = h2u(__floats2half2_rn(v23.x * FSCALE, v23.y * FSCALE));
            q.w = h2u(__floats2half2_rn(v23.z * FSCALE, v23.w * FSCALE));
            *reinterpret_cast<uint4*>(g_htab + (size_t)i * 4) = q;
            return;
        }
        int j = i - htot;
        if (j < npts) {
            float x = __ldg(pos + 3 * (size_t)j + 0);
            float y = __ldg(pos + 3 * (size_t)j + 1);
            float z = __ldg(pos + 3 * (size_t)j + 2);
            g_pos4[j] = make_float4(x, y, z, 0.0f);
        }
        return;
    }

    // ---- dense segment ----
    int j = (int)d_here * 256 + threadIdx.x;
    if (j >= stot) return;

    int l = 0;
    #pragma unroll
    for (int k = 1; k < NDENSE; ++k)
        if (j >= lp.soff[k]) l = k;
    int r = lp.res[l];
    int rm = r - 1;
    int n4 = (r + 3) >> 2;
    int rel = j - lp.soff[l];
    int x = rel % r;
    int t = rel / r;
    int zb = t % n4;
    int yb = t / n4;
    int y0 = yb * 4, z0 = zb * 4;

    unsigned hx = (unsigned)x * P1;
    const float2* tab = tables + (size_t)l * TSZ;
    int base = lp.dofs[l] + x;

    // streamed rows: prev = vertex row y0+a-1, cur = row y0+a
    unsigned prev[5], cur[5];
    {
        unsigned hy = (unsigned)y0 * P2;   // y0 <= r-1 always
        #pragma unroll
        for (int c = 0; c < 5; ++c) {
            int zv = min(z0 + c, rm);
            float2 v = __ldg(tab + ((hx ^ hy ^ ((unsigned)zv * P3)) & TMASK));
            prev[c] = h2u(__floats2half2_rn(v.x * FSCALE, v.y * FSCALE));
        }
    }
    #pragma unroll
    for (int a = 1; a <= 4; ++a) {
        int y = y0 + a - 1;                // cell row emitted this iteration
        if (y >= r) break;
        unsigned hy = (unsigned)min(y0 + a, rm) * P2;
        #pragma unroll
        for (int c = 0; c < 5; ++c) {
            int zv = min(z0 + c, rm);
            float2 v = __ldg(tab + ((hx ^ hy ^ ((unsigned)zv * P3)) & TMASK));
            cur[c] = h2u(__floats2half2_rn(v.x * FSCALE, v.y * FSCALE));
        }
        #pragma unroll
        for (int c = 0; c < 4; ++c) {
            int z = z0 + c;
            if (z >= r) continue;
            uint4 q;
            q.x = prev[c];       // (y,   z)
            q.y = prev[c + 1];   // (y,   z+1)
            q.z = cur[c];        // (y+1, z)
            q.w = cur[c + 1];    // (y+1, z+1)
            g_dense[base + (y * r + z) * r] = q;
        }
        #pragma unroll
        for (int c = 0; c < 5; ++c) prev[c] = cur[c];
    }
}

// ---------------------------------------------------------------------------
// Main kernel (structure from round 9 -- measured at the wavefront floor).
// 16 lanes per point. hl = lane&15, pair k = hl>>1, sub = hl&1.
// Phase A: dense level k    -- lane pair loads adjacent x-cells (shared line ~7/8).
// Phase B: hashed level 8+k -- each lane handles its x-face (4 gathers).
// Positions in [0,1) => floor coords in [0, rm-1], +1 <= rm: no clamps needed.
// Pair reduction: one shfl per feature (cross-phase exchange).
// ---------------------------------------------------------------------------
__global__ void __launch_bounds__(256) hash_enc_main_kernel(
    float2* __restrict__ out,
    int npts, LvlParams lp)
{
    int tid = blockIdx.x * 256 + threadIdx.x;
    int p = tid >> 4;
    if (p >= npts) return;
    int hl = tid & 15;
    int k = hl >> 1;
    int sub = hl & 1;

    float4 ppos = __ldcs(g_pos4 + p);   // read-once: don't pollute L2
    float px = ppos.x, py = ppos.y, pz = ppos.z;

    // ---------- phase A addresses (dense level k) ----------
    int rA = lp.res[k];
    float frA = (float)(rA - 1);
    float sxA = px * frA, syA = py * frA, szA = pz * frA;
    float fxA = floorf(sxA), fyA = floorf(syA), fzA = floorf(szA);
    float wxA = sxA - fxA, wyA = syA - fyA, wzA = szA - fzA;
    int x0A = (int)fxA, y0A = (int)fyA, z0A = (int)fzA;
    const uint4* gA = g_dense + lp.dofs[k];
    uint4 q = __ldg(gA + ((y0A * rA + z0A) * rA + x0A + sub));

    // ---------- phase B addresses (hashed level 8+k) ----------
    int rB = lp.res[8 + k];
    float frB = (float)(rB - 1);
    float sxB = px * frB, syB = py * frB, szB = pz * frB;
    float fxB = floorf(sxB), fyB = floorf(syB), fzB = floorf(szB);
    float wxB = sxB - fxB, wyB = syB - fyB, wzB = szB - fzB;
    int x0B = (int)fxB, y0B = (int)fyB, z0B = (int)fzB;
    unsigned hxB = (unsigned)(x0B + sub) * P1;
    unsigned hy0 = (unsigned)y0B * P2, hy1 = hy0 + P2;
    unsigned hz0 = (unsigned)z0B * P3, hz1 = hz0 + P3;
    const unsigned* ht = g_htab + ((size_t)k << 19);
    unsigned c00u = __ldg(ht + ((hxB ^ hy0 ^ hz0) & TMASK));
    unsigned c01u = __ldg(ht + ((hxB ^ hy0 ^ hz1) & TMASK));
    unsigned c10u = __ldg(ht + ((hxB ^ hy1 ^ hz0) & TMASK));
    unsigned c11u = __ldg(ht + ((hxB ^ hy1 ^ hz1) & TMASK));

    // ---------- phase A math ----------
    float2 a00 = u2f(q.x), a01 = u2f(q.y), a10 = u2f(q.z), a11 = u2f(q.w);
    float wxfA = (sub ? wxA : 1.0f - wxA) * INV_FSCALE;
    float uyA = 1.0f - wyA, uzA = 1.0f - wzA;
    float wA00 = wxfA * uyA * uzA, wA01 = wxfA * uyA * wzA;
    float wA10 = wxfA * wyA * uzA, wA11 = wxfA * wyA * wzA;
    float fA0 = a00.x * wA00, fA1 = a00.y * wA00;
    fA0 = fmaf(a01.x, wA01, fA0);  fA1 = fmaf(a01.y, wA01, fA1);
    fA0 = fmaf(a10.x, wA10, fA0);  fA1 = fmaf(a10.y, wA10, fA1);
    fA0 = fmaf(a11.x, wA11, fA0);  fA1 = fmaf(a11.y, wA11, fA1);

    // ---------- phase B math ----------
    float2 c00 = u2f(c00u), c01 = u2f(c01u), c10 = u2f(c10u), c11 = u2f(c11u);
    float wxfB = (sub ? wxB : 1.0f - wxB) * INV_FSCALE;
    float uyB = 1.0f - wyB, uzB = 1.0f - wzB;
    float wB00 = wxfB * uyB * uzB, wB01 = wxfB * uyB * wzB;
    float wB10 = wxfB * wyB * uzB, wB11 = wxfB * wyB * wzB;
    float fB0 = c00.x * wB00, fB1 = c00.y * wB00;
    fB0 = fmaf(c01.x, wB01, fB0);  fB1 = fmaf(c01.y, wB01, fB1);
    fB0 = fmaf(c10.x, wB10, fB0);  fB1 = fmaf(c10.y, wB10, fB1);
    fB0 = fmaf(c11.x, wB11, fB0);  fB1 = fmaf(c11.y, wB11, fB1);

    // ---------- cross-phase pair reduction: 2 shfls total ----------
    float send0 = sub ? fA0 : fB0;
    float send1 = sub ? fA1 : fB1;
    float recv0 = __shfl_xor_sync(0xFFFFFFFFu, send0, 1);
    float recv1 = __shfl_xor_sync(0xFFFFFFFFu, send1, 1);
    float o0 = (sub ? fB0 : fA0) + recv0;
    float o1 = (sub ? fB1 : fA1) + recv1;

    int lvl = sub ? (8 + k) : k;
    __stcs(out + (size_t)p * 16 + lvl, make_float2(o0, o1));
}

// ---------------------------------------------------------------------------
extern "C" void kernel_launch(void* const* d_in, const int* in_sizes, int n_in,
                              void* d_out, int out_size)
{
    const float*  pos    = (const float*)d_in[0];
    const float2* tables = (const float2*)d_in[1];
    int npts = in_sizes[0] / 3;
    if (npts > POS_CAP) npts = POS_CAP;

    LvlParams lp;
    double b = exp((log(2048.0) - log(16.0)) / 15.0);
    for (int l = 0; l < NLV; ++l) {
        double r = 16.0 * pow(b, (double)l);
        int ri = (int)r;
        if (ri > 2048) ri = 2048;
        lp.res[l] = ri;
    }

    // dense level cell offsets + staging thread offsets (4x4 yz blocks)
    int dtot = 0, stot = 0;
    for (int l = 0; l < NDENSE; ++l) {
        int r = lp.res[l];
        lp.dofs[l] = dtot;
        lp.soff[l] = stot;
        dtot += r * r * r;
        int n4 = (r + 3) / 4;
        stot += r * n4 * n4;
    }

    int htot = (NHASH << 19) / 4;
    int ctot = htot + npts;
    unsigned db = (unsigned)((stot + 255) / 256);
    unsigned cb = (unsigned)((ctot + 255) / 256);
    unsigned T  = db + cb;
    stage_fused_kernel<<<T, 256>>>(tables, pos, lp, htot, npts, stot, db, T);

    long tmain = (long)npts * 16;
    int blocks = (int)((tmain + 255) / 256);
    hash_enc_main_kernel<<<blocks, 256>>>((float2*)d_out, npts, lp);
}

// round 12
// speedup vs baseline: 1.0925x; 1.0925x over previous
#include <cuda_runtime.h>
#include <cuda_fp16.h>
#include <math.h>

#define NLV 16
#define NDENSE 8
#define NHASH 8
#define TSZ (1u << 19)
#define TMASK (TSZ - 1u)
#define P1 2654435761u
#define P2 805459861u
#define P3 3674653429u
#define FSCALE 256.0f
#define INV_FSCALE (1.0f / 256.0f)

// Dense yz-quad grids, x-fastest, fp16x4 per 16B cell. Levels 0..7: ~5.85M cells.
#define DENSE_CAP 6000000
__device__ uint4  g_dense[DENSE_CAP];          // 96 MB
__device__ unsigned g_htab[NHASH << 19];       // fp16x2 copies of tables 8..15 (16 MB)

struct LvlParams {
    int res[NLV];
    int dofs[NDENSE];    // cell offset per dense level
    int soff[NDENSE];    // staging thread offset per dense level (3x3 blocks)
};

__device__ __forceinline__ unsigned h2u(half2 h) { return *reinterpret_cast<unsigned*>(&h); }
__device__ __forceinline__ float2 u2f(unsigned u) {
    half2 h = *reinterpret_cast<half2*>(&u);
    return __half22float2(h);
}

// ---------------------------------------------------------------------------
// Staging kernel, two block-disjoint segments:
//   blocks [0, hb)   : htab fp16 conversion (4 entries/thread)
//   blocks [hb, ...) : dense grid build, 3x3 cell blocks from 4x4 vertices
//                      (16 gathers -> 9 cells), block origin clamped so the
//                      fully-unrolled path always runs; overlap writes are
//                      idempotent.
// ---------------------------------------------------------------------------
__global__ void __launch_bounds__(256) stage_kernel(
    const float2* __restrict__ tables, LvlParams lp, int hb, int stot)
{
    int b = blockIdx.x;
    if (b < hb) {
        int i = b * 256 + threadIdx.x;           // i < htot guaranteed (htot % 256 == 0)
        const float4* src = reinterpret_cast<const float4*>(tables + ((size_t)8 << 19));
        float4 v01 = __ldg(src + (size_t)i * 2);
        float4 v23 = __ldg(src + (size_t)i * 2 + 1);
        uint4 q;
        q.x = h2u(__floats2half2_rn(v01.x * FSCALE, v01.y * FSCALE));
        q.y = h2u(__floats2half2_rn(v01.z * FSCALE, v01.w * FSCALE));
        q.z = h2u(__floats2half2_rn(v23.x * FSCALE, v23.y * FSCALE));
        q.w = h2u(__floats2half2_rn(v23.z * FSCALE, v23.w * FSCALE));
        *reinterpret_cast<uint4*>(g_htab + (size_t)i * 4) = q;
        return;
    }

    int j = (b - hb) * 256 + threadIdx.x;
    if (j >= stot) return;

    int l = 0;
    #pragma unroll
    for (int k = 1; k < NDENSE; ++k)
        if (j >= lp.soff[k]) l = k;
    int r = lp.res[l];
    int rm = r - 1;
    int nb = (r + 2) / 3;
    int rel = j - lp.soff[l];
    int x = rel % r;
    int t = rel / r;
    int zb = t % nb;
    int yb = t / nb;
    int y0 = min(3 * yb, r - 3);
    int z0 = min(3 * zb, r - 3);

    unsigned hx = (unsigned)x * P1;
    const float2* tab = tables + (size_t)l * TSZ;
    int base = lp.dofs[l] + x;

    // stream vertex rows y0..y0+3 (4 cols each); emit 3x3 cells
    unsigned prev0, prev1, prev2, prev3;
    {
        unsigned hy = (unsigned)y0 * P2;
        float2 v0 = __ldg(tab + ((hx ^ hy ^ ((unsigned)(z0 + 0) * P3)) & TMASK));
        float2 v1 = __ldg(tab + ((hx ^ hy ^ ((unsigned)(z0 + 1) * P3)) & TMASK));
        float2 v2 = __ldg(tab + ((hx ^ hy ^ ((unsigned)(z0 + 2) * P3)) & TMASK));
        float2 v3 = __ldg(tab + ((hx ^ hy ^ ((unsigned)min(z0 + 3, rm) * P3)) & TMASK));
        prev0 = h2u(__floats2half2_rn(v0.x * FSCALE, v0.y * FSCALE));
        prev1 = h2u(__floats2half2_rn(v1.x * FSCALE, v1.y * FSCALE));
        prev2 = h2u(__floats2half2_rn(v2.x * FSCALE, v2.y * FSCALE));
        prev3 = h2u(__floats2half2_rn(v3.x * FSCALE, v3.y * FSCALE));
    }
    #pragma unroll
    for (int a = 1; a <= 3; ++a) {
        unsigned hy = (unsigned)min(y0 + a, rm) * P2;
        float2 v0 = __ldg(tab + ((hx ^ hy ^ ((unsigned)(z0 + 0) * P3)) & TMASK));
        float2 v1 = __ldg(tab + ((hx ^ hy ^ ((unsigned)(z0 + 1) * P3)) & TMASK));
        float2 v2 = __ldg(tab + ((hx ^ hy ^ ((unsigned)(z0 + 2) * P3)) & TMASK));
        float2 v3 = __ldg(tab + ((hx ^ hy ^ ((unsigned)min(z0 + 3, rm) * P3)) & TMASK));
        unsigned cur0 = h2u(__floats2half2_rn(v0.x * FSCALE, v0.y * FSCALE));
        unsigned cur1 = h2u(__floats2half2_rn(v1.x * FSCALE, v1.y * FSCALE));
        unsigned cur2 = h2u(__floats2half2_rn(v2.x * FSCALE, v2.y * FSCALE));
        unsigned cur3 = h2u(__floats2half2_rn(v3.x * FSCALE, v3.y * FSCALE));

        int y = y0 + a - 1;
        int rowbase = base + (y * r + z0) * r;
        uint4 q;
        q.x = prev0; q.y = prev1; q.z = cur0; q.w = cur1;
        g_dense[rowbase] = q;
        q.x = prev1; q.y = prev2; q.z = cur1; q.w = cur2;
        g_dense[rowbase + r] = q;
        q.x = prev2; q.y = prev3; q.z = cur2; q.w = cur3;
        g_dense[rowbase + 2 * r] = q;

        prev0 = cur0; prev1 = cur1; prev2 = cur2; prev3 = cur3;
    }
}

// ---------------------------------------------------------------------------
// Main kernel (round-9 structure -- measured at the wavefront floor).
// 16 lanes per point. hl = lane&15, pair k = hl>>1, sub = hl&1.
// Phase A: dense level k    -- lane pair loads adjacent x-cells (shared line ~7/8).
// Phase B: hashed level 8+k -- each lane handles its x-face (4 gathers).
// Positions in [0,1) => floor coords in [0, rm-1], +1 <= rm: no clamps needed.
// Pair reduction: one shfl per feature (cross-phase exchange).
// ---------------------------------------------------------------------------
__global__ void __launch_bounds__(256) hash_enc_main_kernel(
    const float* __restrict__ pos,
    float2* __restrict__ out,
    int npts, LvlParams lp)
{
    int tid = blockIdx.x * 256 + threadIdx.x;
    int p = tid >> 4;
    if (p >= npts) return;
    int hl = tid & 15;
    int k = hl >> 1;
    int sub = hl & 1;

    float px = __ldg(pos + 3 * (size_t)p + 0);
    float py = __ldg(pos + 3 * (size_t)p + 1);
    float pz = __ldg(pos + 3 * (size_t)p + 2);

    // ---------- phase A addresses (dense level k) ----------
    int rA = lp.res[k];
    float frA = (float)(rA - 1);
    float sxA = px * frA, syA = py * frA, szA = pz * frA;
    float fxA = floorf(sxA), fyA = floorf(syA), fzA = floorf(szA);
    float wxA = sxA - fxA, wyA = syA - fyA, wzA = szA - fzA;
    int x0A = (int)fxA, y0A = (int)fyA, z0A = (int)fzA;
    const uint4* gA = g_dense + lp.dofs[k];
    uint4 q = __ldg(gA + ((y0A * rA + z0A) * rA + x0A + sub));

    // ---------- phase B addresses (hashed level 8+k) ----------
    int rB = lp.res[8 + k];
    float frB = (float)(rB - 1);
    float sxB = px * frB, syB = py * frB, szB = pz * frB;
    float fxB = floorf(sxB), fyB = floorf(syB), fzB = floorf(szB);
    float wxB = sxB - fxB, wyB = syB - fyB, wzB = szB - fzB;
    int x0B = (int)fxB, y0B = (int)fyB, z0B = (int)fzB;
    unsigned hxB = (unsigned)(x0B + sub) * P1;
    unsigned hy0 = (unsigned)y0B * P2, hy1 = hy0 + P2;
    unsigned hz0 = (unsigned)z0B * P3, hz1 = hz0 + P3;
    const unsigned* ht = g_htab + ((size_t)k << 19);
    unsigned c00u = __ldg(ht + ((hxB ^ hy0 ^ hz0) & TMASK));
    unsigned c01u = __ldg(ht + ((hxB ^ hy0 ^ hz1) & TMASK));
    unsigned c10u = __ldg(ht + ((hxB ^ hy1 ^ hz0) & TMASK));
    unsigned c11u = __ldg(ht + ((hxB ^ hy1 ^ hz1) & TMASK));

    // ---------- phase A math ----------
    float2 a00 = u2f(q.x), a01 = u2f(q.y), a10 = u2f(q.z), a11 = u2f(q.w);
    float wxfA = (sub ? wxA : 1.0f - wxA) * INV_FSCALE;
    float uyA = 1.0f - wyA, uzA = 1.0f - wzA;
    float wA00 = wxfA * uyA * uzA, wA01 = wxfA * uyA * wzA;
    float wA10 = wxfA * wyA * uzA, wA11 = wxfA * wyA * wzA;
    float fA0 = a00.x * wA00, fA1 = a00.y * wA00;
    fA0 = fmaf(a01.x, wA01, fA0);  fA1 = fmaf(a01.y, wA01, fA1);
    fA0 = fmaf(a10.x, wA10, fA0);  fA1 = fmaf(a10.y, wA10, fA1);
    fA0 = fmaf(a11.x, wA11, fA0);  fA1 = fmaf(a11.y, wA11, fA1);

    // ---------- phase B math ----------
    float2 c00 = u2f(c00u), c01 = u2f(c01u), c10 = u2f(c10u), c11 = u2f(c11u);
    float wxfB = (sub ? wxB : 1.0f - wxB) * INV_FSCALE;
    float uyB = 1.0f - wyB, uzB = 1.0f - wzB;
    float wB00 = wxfB * uyB * uzB, wB01 = wxfB * uyB * wzB;
    float wB10 = wxfB * wyB * uzB, wB11 = wxfB * wyB * wzB;
    float fB0 = c00.x * wB00, fB1 = c00.y * wB00;
    fB0 = fmaf(c01.x, wB01, fB0);  fB1 = fmaf(c01.y, wB01, fB1);
    fB0 = fmaf(c10.x, wB10, fB0);  fB1 = fmaf(c10.y, wB10, fB1);
    fB0 = fmaf(c11.x, wB11, fB0);  fB1 = fmaf(c11.y, wB11, fB1);

    // ---------- cross-phase pair reduction: 2 shfls total ----------
    float send0 = sub ? fA0 : fB0;
    float send1 = sub ? fA1 : fB1;
    float recv0 = __shfl_xor_sync(0xFFFFFFFFu, send0, 1);
    float recv1 = __shfl_xor_sync(0xFFFFFFFFu, send1, 1);
    float o0 = (sub ? fB0 : fA0) + recv0;
    float o1 = (sub ? fB1 : fA1) + recv1;

    int lvl = sub ? (8 + k) : k;
    __stcs(out + (size_t)p * 16 + lvl, make_float2(o0, o1));
}

// ---------------------------------------------------------------------------
extern "C" void kernel_launch(void* const* d_in, const int* in_sizes, int n_in,
                              void* d_out, int out_size)
{
    const float*  pos    = (const float*)d_in[0];
    const float2* tables = (const float2*)d_in[1];
    int npts = in_sizes[0] / 3;

    LvlParams lp;
    double b = exp((log(2048.0) - log(16.0)) / 15.0);
    for (int l = 0; l < NLV; ++l) {
        double r = 16.0 * pow(b, (double)l);
        int ri = (int)r;
        if (ri > 2048) ri = 2048;
        lp.res[l] = ri;
    }

    // dense level cell offsets + staging thread offsets (3x3 cell blocks)
    int dtot = 0, stot = 0;
    for (int l = 0; l < NDENSE; ++l) {
        int r = lp.res[l];
        lp.dofs[l] = dtot;
        lp.soff[l] = stot;
        dtot += r * r * r;
        int nb = (r + 2) / 3;
        stot += r * nb * nb;
    }

    int htot = (NHASH << 19) / 4;            // 1M threads, multiple of 256
    int hb = htot / 256;
    int db = (stot + 255) / 256;
    stage_kernel<<<hb + db, 256>>>(tables, lp, hb, stot);

    long tmain = (long)npts * 16;
    int blocks = (int)((tmain + 255) / 256);
    hash_enc_main_kernel<<<blocks, 256>>>(pos, (float2*)d_out, npts, lp);
}

// round 13
// speedup vs baseline: 1.0957x; 1.0029x over previous
#include <cuda_runtime.h>
#include <cuda_fp16.h>
#include <math.h>

#define NLV 16
#define NDENSE 8
#define NHASH 8
#define TSZ (1u << 19)
#define TMASK (TSZ - 1u)
#define P1 2654435761u
#define P2 805459861u
#define P3 3674653429u
#define FSCALE 256.0f
#define INV_FSCALE (1.0f / 256.0f)

// Dense yz-quad grids, x-fastest, fp16x4 per 16B cell. Levels 0..7: ~5.85M cells.
#define DENSE_CAP 6000000
__device__ uint4  g_dense[DENSE_CAP];          // 96 MB
__device__ unsigned g_htab[NHASH << 19];       // fp16x2 copies of tables 8..15 (16 MB)

struct LvlParams {
    int res[NLV];
    int dofs[NDENSE];    // cell offset per dense level
    int soff[NDENSE];    // staging thread offset per dense level (4x4 blocks)
};

__device__ __forceinline__ unsigned h2u(half2 h) { return *reinterpret_cast<unsigned*>(&h); }
__device__ __forceinline__ float2 u2f(unsigned u) {
    half2 h = *reinterpret_cast<half2*>(&u);
    return __half22float2(h);
}

__device__ __forceinline__ unsigned gat(const float2* __restrict__ tab,
                                        unsigned hx, unsigned hy, unsigned hz) {
    float2 v = __ldg(tab + ((hx ^ hy ^ hz) & TMASK));
    return h2u(__floats2half2_rn(v.x * FSCALE, v.y * FSCALE));
}

// ---------------------------------------------------------------------------
// Staging kernel, two block-disjoint segments:
//   blocks [0, hb)   : htab fp16 conversion (4 entries/thread)
//   blocks [hb, ...) : dense grid build, 4x4 cell blocks from 5x5 vertices
//                      (25 gathers -> 16 cells), named scalar registers only,
//                      block origin clamped so the fully-unrolled path always
//                      runs; overlap writes are idempotent.
// ---------------------------------------------------------------------------
__global__ void __launch_bounds__(256) stage_kernel(
    const float2* __restrict__ tables, LvlParams lp, int hb, int stot)
{
    int b = blockIdx.x;
    if (b < hb) {
        int i = b * 256 + threadIdx.x;           // i < htot guaranteed (htot % 256 == 0)
        const float4* src = reinterpret_cast<const float4*>(tables + ((size_t)8 << 19));
        float4 v01 = __ldg(src + (size_t)i * 2);
        float4 v23 = __ldg(src + (size_t)i * 2 + 1);
        uint4 q;
        q.x = h2u(__floats2half2_rn(v01.x * FSCALE, v01.y * FSCALE));
        q.y = h2u(__floats2half2_rn(v01.z * FSCALE, v01.w * FSCALE));
        q.z = h2u(__floats2half2_rn(v23.x * FSCALE, v23.y * FSCALE));
        q.w = h2u(__floats2half2_rn(v23.z * FSCALE, v23.w * FSCALE));
        *reinterpret_cast<uint4*>(g_htab + (size_t)i * 4) = q;
        return;
    }

    int j = (b - hb) * 256 + threadIdx.x;
    if (j >= stot) return;

    int l = 0;
    #pragma unroll
    for (int k = 1; k < NDENSE; ++k)
        if (j >= lp.soff[k]) l = k;
    int r = lp.res[l];
    int rm = r - 1;
    int nb = (r + 3) / 4;
    int rel = j - lp.soff[l];
    int x = rel % r;
    int t = rel / r;
    int zb = t % nb;
    int yb = t / nb;
    int y0 = min(4 * yb, r - 4);     // r >= 16 so r-4 >= 0; overlap is idempotent
    int z0 = min(4 * zb, r - 4);

    unsigned hx = (unsigned)x * P1;
    const float2* tab = tables + (size_t)l * TSZ;
    int base = lp.dofs[l] + x;

    unsigned hz0 = (unsigned)(z0 + 0) * P3;
    unsigned hz1 = (unsigned)(z0 + 1) * P3;
    unsigned hz2 = (unsigned)(z0 + 2) * P3;
    unsigned hz3 = (unsigned)(z0 + 3) * P3;
    unsigned hz4 = (unsigned)min(z0 + 4, rm) * P3;

    // stream vertex rows y0..y0+4 (5 cols each); emit 4x4 cells
    unsigned p0, p1, p2, p3, p4;
    {
        unsigned hy = (unsigned)y0 * P2;
        p0 = gat(tab, hx, hy, hz0);
        p1 = gat(tab, hx, hy, hz1);
        p2 = gat(tab, hx, hy, hz2);
        p3 = gat(tab, hx, hy, hz3);
        p4 = gat(tab, hx, hy, hz4);
    }
    #pragma unroll
    for (int a = 1; a <= 4; ++a) {
        unsigned hy = (unsigned)min(y0 + a, rm) * P2;
        unsigned c0 = gat(tab, hx, hy, hz0);
        unsigned c1 = gat(tab, hx, hy, hz1);
        unsigned c2 = gat(tab, hx, hy, hz2);
        unsigned c3 = gat(tab, hx, hy, hz3);
        unsigned c4 = gat(tab, hx, hy, hz4);

        int y = y0 + a - 1;
        int rowbase = base + (y * r + z0) * r;
        uint4 q;
        q.x = p0; q.y = p1; q.z = c0; q.w = c1;
        g_dense[rowbase] = q;
        q.x = p1; q.y = p2; q.z = c1; q.w = c2;
        g_dense[rowbase + r] = q;
        q.x = p2; q.y = p3; q.z = c2; q.w = c3;
        g_dense[rowbase + 2 * r] = q;
        q.x = p3; q.y = p4; q.z = c3; q.w = c4;
        g_dense[rowbase + 3 * r] = q;

        p0 = c0; p1 = c1; p2 = c2; p3 = c3; p4 = c4;
    }
}

// ---------------------------------------------------------------------------
// Main kernel (round-9 structure -- measured at the wavefront floor).
// 16 lanes per point. hl = lane&15, pair k = hl>>1, sub = hl&1.
// Phase A: dense level k    -- lane pair loads adjacent x-cells (shared line ~7/8).
// Phase B: hashed level 8+k -- each lane handles its x-face (4 gathers).
// Positions in [0,1) => floor coords in [0, rm-1], +1 <= rm: no clamps needed.
// Pair reduction: one shfl per feature (cross-phase exchange).
// ---------------------------------------------------------------------------
__global__ void __launch_bounds__(256) hash_enc_main_kernel(
    const float* __restrict__ pos,
    float2* __restrict__ out,
    int npts, LvlParams lp)
{
    int tid = blockIdx.x * 256 + threadIdx.x;
    int p = tid >> 4;
    if (p >= npts) return;
    int hl = tid & 15;
    int k = hl >> 1;
    int sub = hl & 1;

    float px = __ldg(pos + 3 * (size_t)p + 0);
    float py = __ldg(pos + 3 * (size_t)p + 1);
    float pz = __ldg(pos + 3 * (size_t)p + 2);

    // ---------- phase A addresses (dense level k) ----------
    int rA = lp.res[k];
    float frA = (float)(rA - 1);
    float sxA = px * frA, syA = py * frA, szA = pz * frA;
    float fxA = floorf(sxA), fyA = floorf(syA), fzA = floorf(szA);
    float wxA = sxA - fxA, wyA = syA - fyA, wzA = szA - fzA;
    int x0A = (int)fxA, y0A = (int)fyA, z0A = (int)fzA;
    const uint4* gA = g_dense + lp.dofs[k];
    uint4 q = __ldg(gA + ((y0A * rA + z0A) * rA + x0A + sub));

    // ---------- phase B addresses (hashed level 8+k) ----------
    int rB = lp.res[8 + k];
    float frB = (float)(rB - 1);
    float sxB = px * frB, syB = py * frB, szB = pz * frB;
    float fxB = floorf(sxB), fyB = floorf(syB), fzB = floorf(szB);
    float wxB = sxB - fxB, wyB = syB - fyB, wzB = szB - fzB;
    int x0B = (int)fxB, y0B = (int)fyB, z0B = (int)fzB;
    unsigned hxB = (unsigned)(x0B + sub) * P1;
    unsigned hy0 = (unsigned)y0B * P2, hy1 = hy0 + P2;
    unsigned hz0 = (unsigned)z0B * P3, hz1 = hz0 + P3;
    const unsigned* ht = g_htab + ((size_t)k << 19);
    unsigned c00u = __ldg(ht + ((hxB ^ hy0 ^ hz0) & TMASK));
    unsigned c01u = __ldg(ht + ((hxB ^ hy0 ^ hz1) & TMASK));
    unsigned c10u = __ldg(ht + ((hxB ^ hy1 ^ hz0) & TMASK));
    unsigned c11u = __ldg(ht + ((hxB ^ hy1 ^ hz1) & TMASK));

    // ---------- phase A math ----------
    float2 a00 = u2f(q.x), a01 = u2f(q.y), a10 = u2f(q.z), a11 = u2f(q.w);
    float wxfA = (sub ? wxA : 1.0f - wxA) * INV_FSCALE;
    float uyA = 1.0f - wyA, uzA = 1.0f - wzA;
    float wA00 = wxfA * uyA * uzA, wA01 = wxfA * uyA * wzA;
    float wA10 = wxfA * wyA * uzA, wA11 = wxfA * wyA * wzA;
    float fA0 = a00.x * wA00, fA1 = a00.y * wA00;
    fA0 = fmaf(a01.x, wA01, fA0);  fA1 = fmaf(a01.y, wA01, fA1);
    fA0 = fmaf(a10.x, wA10, fA0);  fA1 = fmaf(a10.y, wA10, fA1);
    fA0 = fmaf(a11.x, wA11, fA0);  fA1 = fmaf(a11.y, wA11, fA1);

    // ---------- phase B math ----------
    float2 c00 = u2f(c00u), c01 = u2f(c01u), c10 = u2f(c10u), c11 = u2f(c11u);
    float wxfB = (sub ? wxB : 1.0f - wxB) * INV_FSCALE;
    float uyB = 1.0f - wyB, uzB = 1.0f - wzB;
    float wB00 = wxfB * uyB * uzB, wB01 = wxfB * uyB * wzB;
    float wB10 = wxfB * wyB * uzB, wB11 = wxfB * wyB * wzB;
    float fB0 = c00.x * wB00, fB1 = c00.y * wB00;
    fB0 = fmaf(c01.x, wB01, fB0);  fB1 = fmaf(c01.y, wB01, fB1);
    fB0 = fmaf(c10.x, wB10, fB0);  fB1 = fmaf(c10.y, wB10, fB1);
    fB0 = fmaf(c11.x, wB11, fB0);  fB1 = fmaf(c11.y, wB11, fB1);

    // ---------- cross-phase pair reduction: 2 shfls total ----------
    float send0 = sub ? fA0 : fB0;
    float send1 = sub ? fA1 : fB1;
    float recv0 = __shfl_xor_sync(0xFFFFFFFFu, send0, 1);
    float recv1 = __shfl_xor_sync(0xFFFFFFFFu, send1, 1);
    float o0 = (sub ? fB0 : fA0) + recv0;
    float o1 = (sub ? fB1 : fA1) + recv1;

    int lvl = sub ? (8 + k) : k;
    __stcs(out + (size_t)p * 16 + lvl, make_float2(o0, o1));
}

// ---------------------------------------------------------------------------
extern "C" void kernel_launch(void* const* d_in, const int* in_sizes, int n_in,
                              void* d_out, int out_size)
{
    const float*  pos    = (const float*)d_in[0];
    const float2* tables = (const float2*)d_in[1];
    int npts = in_sizes[0] / 3;

    LvlParams lp;
    double b = exp((log(2048.0) - log(16.0)) / 15.0);
    for (int l = 0; l < NLV; ++l) {
        double r = 16.0 * pow(b, (double)l);
        int ri = (int)r;
        if (ri > 2048) ri = 2048;
        lp.res[l] = ri;
    }

    // dense level cell offsets + staging thread offsets (4x4 cell blocks)
    int dtot = 0, stot = 0;
    for (int l = 0; l < NDENSE; ++l) {
        int r = lp.res[l];
        lp.dofs[l] = dtot;
        lp.soff[l] = stot;
        dtot += r * r * r;
        int nb = (r + 3) / 4;
        stot += r * nb * nb;
    }

    int htot = (NHASH << 19) / 4;            // 1M threads, multiple of 256
    int hb = htot / 256;
    int db = (stot + 255) / 256;
    stage_kernel<<<hb + db, 256>>>(tables, lp, hb, stot);

    long tmain = (long)npts * 16;
    int blocks = (int)((tmain + 255) / 256);
    hash_enc_main_kernel<<<blocks, 256>>>(pos, (float2*)d_out, npts, lp);
}

// round 14
// speedup vs baseline: 1.1005x; 1.0044x over previous
#include <cuda_runtime.h>
#include <cuda_fp16.h>
#include <math.h>

#define NLV 16
#define NDENSE 8
#define NHASH 8
#define TSZ (1u << 19)
#define TMASK (TSZ - 1u)
#define P1 2654435761u
#define P2 805459861u
#define P3 3674653429u
#define FSCALE 256.0f
#define INV_FSCALE (1.0f / 256.0f)

// Dense yz-quad grids, x-fastest, fp16x4 per 16B cell. Levels 0..7: ~5.85M cells.
#define DENSE_CAP 6000000
__device__ uint4  g_dense[DENSE_CAP];          // 96 MB
__device__ unsigned g_htab[NHASH << 19];       // fp16x2 copies of tables 8..15 (16 MB)

struct LvlParams {
    int res[NLV];
    int dofs[NDENSE];    // cell offset per dense level
    int soff[NDENSE];    // staging thread offset per dense level (8x8 blocks)
};

__device__ __forceinline__ unsigned h2u(half2 h) { return *reinterpret_cast<unsigned*>(&h); }
__device__ __forceinline__ float2 u2f(unsigned u) {
    half2 h = *reinterpret_cast<half2*>(&u);
    return __half22float2(h);
}

__device__ __forceinline__ unsigned gat(const float2* __restrict__ tab,
                                        unsigned hx, unsigned hy, unsigned hz) {
    float2 v = __ldg(tab + ((hx ^ hy ^ hz) & TMASK));
    return h2u(__floats2half2_rn(v.x * FSCALE, v.y * FSCALE));
}

// ---------------------------------------------------------------------------
// Staging kernel, two block-disjoint segments (dense FIRST so the long pole
// starts immediately; DRAM-bound htab blocks fill the tail):
//   blocks [0, db)   : dense grid build, 8x8 cell blocks from 9x9 vertices
//                      (81 gathers -> 64 cells), named scalar registers only,
//                      block origin clamped; overlap writes are idempotent.
//   blocks [db, ...) : htab fp16 conversion (4 entries/thread)
// ---------------------------------------------------------------------------
__global__ void __launch_bounds__(256) stage_kernel(
    const float2* __restrict__ tables, LvlParams lp, int db, int stot)
{
    int b = blockIdx.x;
    if (b >= db) {
        int i = (b - db) * 256 + threadIdx.x;    // i < htot guaranteed (htot % 256 == 0)
        const float4* src = reinterpret_cast<const float4*>(tables + ((size_t)8 << 19));
        float4 v01 = __ldg(src + (size_t)i * 2);
        float4 v23 = __ldg(src + (size_t)i * 2 + 1);
        uint4 q;
        q.x = h2u(__floats2half2_rn(v01.x * FSCALE, v01.y * FSCALE));
        q.y = h2u(__floats2half2_rn(v01.z * FSCALE, v01.w * FSCALE));
        q.z = h2u(__floats2half2_rn(v23.x * FSCALE, v23.y * FSCALE));
        q.w = h2u(__floats2half2_rn(v23.z * FSCALE, v23.w * FSCALE));
        *reinterpret_cast<uint4*>(g_htab + (size_t)i * 4) = q;
        return;
    }

    int j = b * 256 + threadIdx.x;
    if (j >= stot) return;

    int l = 0;
    #pragma unroll
    for (int k = 1; k < NDENSE; ++k)
        if (j >= lp.soff[k]) l = k;
    int r = lp.res[l];
    int rm = r - 1;
    int nb = (r + 7) / 8;
    int rel = j - lp.soff[l];
    int x = rel % r;
    int t = rel / r;
    int zb = t % nb;
    int yb = t / nb;
    int y0 = min(8 * yb, r - 8);     // r >= 16 so r-8 >= 0; overlap is idempotent
    int z0 = min(8 * zb, r - 8);

    unsigned hx = (unsigned)x * P1;
    const float2* tab = tables + (size_t)l * TSZ;
    int base = lp.dofs[l] + x;

    unsigned hz0 = (unsigned)(z0 + 0) * P3;
    unsigned hz1 = (unsigned)(z0 + 1) * P3;
    unsigned hz2 = (unsigned)(z0 + 2) * P3;
    unsigned hz3 = (unsigned)(z0 + 3) * P3;
    unsigned hz4 = (unsigned)(z0 + 4) * P3;
    unsigned hz5 = (unsigned)(z0 + 5) * P3;
    unsigned hz6 = (unsigned)(z0 + 6) * P3;
    unsigned hz7 = (unsigned)(z0 + 7) * P3;
    unsigned hz8 = (unsigned)min(z0 + 8, rm) * P3;

    // stream vertex rows y0..y0+8 (9 cols each); emit 8x8 cells
    unsigned p0, p1, p2, p3, p4, p5, p6, p7, p8;
    {
        unsigned hy = (unsigned)y0 * P2;
        p0 = gat(tab, hx, hy, hz0);
        p1 = gat(tab, hx, hy, hz1);
        p2 = gat(tab, hx, hy, hz2);
        p3 = gat(tab, hx, hy, hz3);
        p4 = gat(tab, hx, hy, hz4);
        p5 = gat(tab, hx, hy, hz5);
        p6 = gat(tab, hx, hy, hz6);
        p7 = gat(tab, hx, hy, hz7);
        p8 = gat(tab, hx, hy, hz8);
    }
    #pragma unroll
    for (int a = 1; a <= 8; ++a) {
        unsigned hy = (unsigned)min(y0 + a, rm) * P2;
        unsigned c0 = gat(tab, hx, hy, hz0);
        unsigned c1 = gat(tab, hx, hy, hz1);
        unsigned c2 = gat(tab, hx, hy, hz2);
        unsigned c3 = gat(tab, hx, hy, hz3);
        unsigned c4 = gat(tab, hx, hy, hz4);
        unsigned c5 = gat(tab, hx, hy, hz5);
        unsigned c6 = gat(tab, hx, hy, hz6);
        unsigned c7 = gat(tab, hx, hy, hz7);
        unsigned c8 = gat(tab, hx, hy, hz8);

        int y = y0 + a - 1;
        int rowbase = base + (y * r + z0) * r;
        uint4 q;
        q.x = p0; q.y = p1; q.z = c0; q.w = c1;  g_dense[rowbase]         = q;
        q.x = p1; q.y = p2; q.z = c1; q.w = c2;  g_dense[rowbase + r]     = q;
        q.x = p2; q.y = p3; q.z = c2; q.w = c3;  g_dense[rowbase + 2 * r] = q;
        q.x = p3; q.y = p4; q.z = c3; q.w = c4;  g_dense[rowbase + 3 * r] = q;
        q.x = p4; q.y = p5; q.z = c4; q.w = c5;  g_dense[rowbase + 4 * r] = q;
        q.x = p5; q.y = p6; q.z = c5; q.w = c6;  g_dense[rowbase + 5 * r] = q;
        q.x = p6; q.y = p7; q.z = c6; q.w = c7;  g_dense[rowbase + 6 * r] = q;
        q.x = p7; q.y = p8; q.z = c7; q.w = c8;  g_dense[rowbase + 7 * r] = q;

        p0 = c0; p1 = c1; p2 = c2; p3 = c3; p4 = c4;
        p5 = c5; p6 = c6; p7 = c7; p8 = c8;
    }
}

// ---------------------------------------------------------------------------
// Main kernel (round-9 structure -- measured at the wavefront floor).
// 16 lanes per point. hl = lane&15, pair k = hl>>1, sub = hl&1.
// Phase A: dense level k    -- lane pair loads adjacent x-cells (shared line ~7/8).
// Phase B: hashed level 8+k -- each lane handles its x-face (4 gathers).
// Positions in [0,1) => floor coords in [0, rm-1], +1 <= rm: no clamps needed.
// Pair reduction: one shfl per feature (cross-phase exchange).
// ---------------------------------------------------------------------------
__global__ void __launch_bounds__(256) hash_enc_main_kernel(
    const float* __restrict__ pos,
    float2* __restrict__ out,
    int npts, LvlParams lp)
{
    int tid = blockIdx.x * 256 + threadIdx.x;
    int p = tid >> 4;
    if (p >= npts) return;
    int hl = tid & 15;
    int k = hl >> 1;
    int sub = hl & 1;

    float px = __ldg(pos + 3 * (size_t)p + 0);
    float py = __ldg(pos + 3 * (size_t)p + 1);
    float pz = __ldg(pos + 3 * (size_t)p + 2);

    // ---------- phase A addresses (dense level k) ----------
    int rA = lp.res[k];
    float frA = (float)(rA - 1);
    float sxA = px * frA, syA = py * frA, szA = pz * frA;
    float fxA = floorf(sxA), fyA = floorf(syA), fzA = floorf(szA);
    float wxA = sxA - fxA, wyA = syA - fyA, wzA = szA - fzA;
    int x0A = (int)fxA, y0A = (int)fyA, z0A = (int)fzA;
    const uint4* gA = g_dense + lp.dofs[k];
    uint4 q = __ldg(gA + ((y0A * rA + z0A) * rA + x0A + sub));

    // ---------- phase B addresses (hashed level 8+k) ----------
    int rB = lp.res[8 + k];
    float frB = (float)(rB - 1);
    float sxB = px * frB, syB = py * frB, szB = pz * frB;
    float fxB = floorf(sxB), fyB = floorf(syB), fzB = floorf(szB);
    float wxB = sxB - fxB, wyB = syB - fyB, wzB = szB - fzB;
    int x0B = (int)fxB, y0B = (int)fyB, z0B = (int)fzB;
    unsigned hxB = (unsigned)(x0B + sub) * P1;
    unsigned hy0 = (unsigned)y0B * P2, hy1 = hy0 + P2;
    unsigned hz0 = (unsigned)z0B * P3, hz1 = hz0 + P3;
    const unsigned* ht = g_htab + ((size_t)k << 19);
    unsigned c00u = __ldg(ht + ((hxB ^ hy0 ^ hz0) & TMASK));
    unsigned c01u = __ldg(ht + ((hxB ^ hy0 ^ hz1) & TMASK));
    unsigned c10u = __ldg(ht + ((hxB ^ hy1 ^ hz0) & TMASK));
    unsigned c11u = __ldg(ht + ((hxB ^ hy1 ^ hz1) & TMASK));

    // ---------- phase A math ----------
    float2 a00 = u2f(q.x), a01 = u2f(q.y), a10 = u2f(q.z), a11 = u2f(q.w);
    float wxfA = (sub ? wxA : 1.0f - wxA) * INV_FSCALE;
    float uyA = 1.0f - wyA, uzA = 1.0f - wzA;
    float wA00 = wxfA * uyA * uzA, wA01 = wxfA * uyA * wzA;
    float wA10 = wxfA * wyA * uzA, wA11 = wxfA * wyA * wzA;
    float fA0 = a00.x * wA00, fA1 = a00.y * wA00;
    fA0 = fmaf(a01.x, wA01, fA0);  fA1 = fmaf(a01.y, wA01, fA1);
    fA0 = fmaf(a10.x, wA10, fA0);  fA1 = fmaf(a10.y, wA10, fA1);
    fA0 = fmaf(a11.x, wA11, fA0);  fA1 = fmaf(a11.y, wA11, fA1);

    // ---------- phase B math ----------
    float2 c00 = u2f(c00u), c01 = u2f(c01u), c10 = u2f(c10u), c11 = u2f(c11u);
    float wxfB = (sub ? wxB : 1.0f - wxB) * INV_FSCALE;
    float uyB = 1.0f - wyB, uzB = 1.0f - wzB;
    float wB00 = wxfB * uyB * uzB, wB01 = wxfB * uyB * wzB;
    float wB10 = wxfB * wyB * uzB, wB11 = wxfB * wyB * wzB;
    float fB0 = c00.x * wB00, fB1 = c00.y * wB00;
    fB0 = fmaf(c01.x, wB01, fB0);  fB1 = fmaf(c01.y, wB01, fB1);
    fB0 = fmaf(c10.x, wB10, fB0);  fB1 = fmaf(c10.y, wB10, fB1);
    fB0 = fmaf(c11.x, wB11, fB0);  fB1 = fmaf(c11.y, wB11, fB1);

    // ---------- cross-phase pair reduction: 2 shfls total ----------
    float send0 = sub ? fA0 : fB0;
    float send1 = sub ? fA1 : fB1;
    float recv0 = __shfl_xor_sync(0xFFFFFFFFu, send0, 1);
    float recv1 = __shfl_xor_sync(0xFFFFFFFFu, send1, 1);
    float o0 = (sub ? fB0 : fA0) + recv0;
    float o1 = (sub ? fB1 : fA1) + recv1;

    int lvl = sub ? (8 + k) : k;
    __stcs(out + (size_t)p * 16 + lvl, make_float2(o0, o1));
}

// ---------------------------------------------------------------------------
extern "C" void kernel_launch(void* const* d_in, const int* in_sizes, int n_in,
                              void* d_out, int out_size)
{
    const float*  pos    = (const float*)d_in[0];
    const float2* tables = (const float2*)d_in[1];
    int npts = in_sizes[0] / 3;

    LvlParams lp;
    double b = exp((log(2048.0) - log(16.0)) / 15.0);
    for (int l = 0; l < NLV; ++l) {
        double r = 16.0 * pow(b, (double)l);
        int ri = (int)r;
        if (ri > 2048) ri = 2048;
        lp.res[l] = ri;
    }

    // dense level cell offsets + staging thread offsets (8x8 cell blocks)
    int dtot = 0, stot = 0;
    for (int l = 0; l < NDENSE; ++l) {
        int r = lp.res[l];
        lp.dofs[l] = dtot;
        lp.soff[l] = stot;
        dtot += r * r * r;
        int nb = (r + 7) / 8;
        stot += r * nb * nb;
    }

    int htot = (NHASH << 19) / 4;            // 1M threads, multiple of 256
    int hb = htot / 256;
    int db = (stot + 255) / 256;
    stage_kernel<<<db + hb, 256>>>(tables, lp, db, stot);

    long tmain = (long)npts * 16;
    int blocks = (int)((tmain + 255) / 256);
    hash_enc_main_kernel<<<blocks, 256>>>(pos, (float2*)d_out, npts, lp);
}